// round 3
// baseline (speedup 1.0000x reference)
#include <cuda_runtime.h>
#include <cuda_bf16.h>
#include <cstdint>

// ---------------- problem constants ----------------
#define BATCH   16
#define NTOK    577
#define CDIM    1024
#define HEADS   16
#define HDIM    64
#define HIDDEN  4096
#define MROWS   (BATCH * NTOK)     // 9232
#define NPAD    640                // seq padded to 5*128
#define BH      (BATCH * HEADS)    // 256
#define QKVC    (3 * CDIM)         // 3072

// ---------------- scratch (device globals; no allocs allowed) ----------------
__device__ float g_h  [MROWS * CDIM];        // LN1 out (tf32-rounded)
__device__ float g_qkv[(long)MROWS * QKVC];  // fused q|k|v, row stride 3072
__device__ float g_S  [(long)BH * NPAD * NPAD];  // scores, then P in-place
__device__ float g_Vt [(long)BH * HDIM * NPAD];  // V^T per head, zero-padded
__device__ float g_o  [MROWS * CDIM];        // attention out (packed)
__device__ float g_x1 [MROWS * CDIM];        // x + proj (fp32 exact)
__device__ float g_h2 [MROWS * CDIM];        // LN2 out
__device__ float g_m1 [(long)MROWS * HIDDEN];
__device__ float g_Wqkv[QKVC * CDIM];
__device__ float g_Wp [CDIM * CDIM];
__device__ float g_W1 [HIDDEN * CDIM];
__device__ float g_W2 [CDIM * HIDDEN];

// ---------------- helpers ----------------
__device__ __forceinline__ float tf32r(float x) {
    asm("cvt.rna.tf32.f32 %0, %1;" : "=f"(x) : "f"(x));
    return x;
}

__global__ void cvt_kernel(const float* __restrict__ src, float* __restrict__ dst, int n) {
    int i = blockIdx.x * 256 + threadIdx.x;
    if (i < n) dst[i] = tf32r(src[i]);
}

// ---------------- LayerNorm (row = 1024) ----------------
__global__ __launch_bounds__(256) void ln_kernel(
    const float* __restrict__ x, const float* __restrict__ gw,
    const float* __restrict__ bw, float* __restrict__ out)
{
    long row = blockIdx.x;
    const float* xr = x + row * CDIM;
    float* orow = out + row * CDIM;
    int tid = threadIdx.x;
    float v[4]; float s = 0.f, sq = 0.f;
#pragma unroll
    for (int i = 0; i < 4; i++) { v[i] = xr[tid + 256 * i]; s += v[i]; sq += v[i] * v[i]; }
#pragma unroll
    for (int o = 16; o > 0; o >>= 1) {
        s  += __shfl_xor_sync(0xffffffffu, s,  o);
        sq += __shfl_xor_sync(0xffffffffu, sq, o);
    }
    __shared__ float ss[8], qq[8];
    int warp = tid >> 5, lane = tid & 31;
    if (lane == 0) { ss[warp] = s; qq[warp] = sq; }
    __syncthreads();
    float ts = 0.f, tq = 0.f;
#pragma unroll
    for (int i = 0; i < 8; i++) { ts += ss[i]; tq += qq[i]; }
    float mean = ts * (1.f / CDIM);
    float var  = tq * (1.f / CDIM) - mean * mean;
    float rsd  = rsqrtf(var + 1e-5f);
#pragma unroll
    for (int i = 0; i < 4; i++) {
        int c = tid + 256 * i;
        orow[c] = tf32r((v[i] - mean) * rsd * gw[c] + bw[c]);
    }
}

// ---------------- softmax (in-place on S rows; writes zero padding) ----------------
__global__ __launch_bounds__(256) void softmax_kernel(float* __restrict__ S) {
    int q = blockIdx.x;
    int z = blockIdx.y;
    float* row = S + (long)z * NPAD * NPAD + (long)q * NPAD;
    int tid = threadIdx.x;
    int warp = tid >> 5, lane = tid & 31;

    float v[3]; float mx = -1e30f;
#pragma unroll
    for (int i = 0; i < 3; i++) {
        int c = tid + 256 * i;
        v[i] = (c < NTOK) ? row[c] : -1e30f;
        mx = fmaxf(mx, v[i]);
    }
#pragma unroll
    for (int o = 16; o > 0; o >>= 1) mx = fmaxf(mx, __shfl_xor_sync(0xffffffffu, mx, o));
    __shared__ float red[8];
    if (lane == 0) red[warp] = mx;
    __syncthreads();
    float m2 = red[0];
#pragma unroll
    for (int i = 1; i < 8; i++) m2 = fmaxf(m2, red[i]);
    __syncthreads();

    float e[3]; float s = 0.f;
#pragma unroll
    for (int i = 0; i < 3; i++) {
        int c = tid + 256 * i;
        e[i] = (c < NTOK) ? __expf(v[i] - m2) : 0.f;
        s += e[i];
    }
#pragma unroll
    for (int o = 16; o > 0; o >>= 1) s += __shfl_xor_sync(0xffffffffu, s, o);
    if (lane == 0) red[warp] = s;
    __syncthreads();
    float tot = 0.f;
#pragma unroll
    for (int i = 0; i < 8; i++) tot += red[i];
    float inv = 1.f / tot;
#pragma unroll
    for (int i = 0; i < 3; i++) {
        int c = tid + 256 * i;
        if (c < NPAD) row[c] = (c < NTOK) ? tf32r(e[i] * inv) : 0.f;
    }
}

// ---------------- V transpose: v[(b*577+k)*ldv + h*64 + d] -> Vt[z][d][k(pad 640)] ----------------
__global__ __launch_bounds__(256) void vtrans_kernel(
    const float* __restrict__ v, int ldv, float* __restrict__ Vt)
{
    int kb = blockIdx.x;
    int z  = blockIdx.y;
    int bb = z >> 4, hh = z & 15;
    __shared__ float tile[32][65];
    int tid = threadIdx.x;
#pragma unroll
    for (int e = 0; e < 8; e++) {
        int idx = tid + e * 256;
        int kk = idx >> 6, dd = idx & 63;
        int kg = kb * 32 + kk;
        tile[kk][dd] = (kg < NTOK)
            ? v[((long)(bb * NTOK + kg)) * ldv + hh * HDIM + dd] : 0.f;
    }
    __syncthreads();
#pragma unroll
    for (int e = 0; e < 8; e++) {
        int idx = tid + e * 256;
        int dd = idx >> 5, kk = idx & 31;
        Vt[(long)z * HDIM * NPAD + (long)dd * NPAD + kb * 32 + kk] = tile[kk][dd];
    }
}

// ---------------- cp.async multi-stage tf32 tensor-core GEMM ----------------
// C[m][n] = alpha * sum_k A[m][k] * B[n][k]  (+bias, +act, +res)
// MODE 0: dense.  MODE 1: per-(b,h) QK^T -> S.  MODE 2: per-(b,h) P*V^T -> o scattered.
#define BM 128
#define BN 128
#define BKT 16
#define LDS_ 20           // padded row stride (floats): conflict-free, 16B-aligned
#define STAGES 4
#define STG_SZ ((BM + BN) * LDS_)                 // floats per stage
#define GEMM_SMEM_BYTES (STAGES * STG_SZ * 4)     // 81920

__device__ __forceinline__ void cp16(float* dst, const float* src, int sz) {
    uint32_t d = (uint32_t)__cvta_generic_to_shared(dst);
    asm volatile("cp.async.cg.shared.global [%0], [%1], 16, %2;\n"
                 :: "r"(d), "l"(src), "r"(sz));
}

template<int MODE, int ACT, bool TF32OUT, bool HAS_BIAS, bool HAS_RES>
__global__ __launch_bounds__(256) void gemm_cp(
    const float* __restrict__ A, int lda,
    const float* __restrict__ Bw, int ldb,
    float* __restrict__ Cout, int ldc,
    const float* __restrict__ bias,
    const float* __restrict__ res,
    int M, int Nn, int K, float alpha)
{
    extern __shared__ float smem_dyn[];

    int tid  = threadIdx.x;
    int lane = tid & 31;
    int warp = tid >> 5;
    int wm = (warp >> 2) * 64;
    int wn = (warp & 3) * 32;

    long aOff = 0, bOff = 0, cOff = 0;
    if (MODE == 1) {
        int bb = blockIdx.z >> 4, hh = blockIdx.z & 15;
        aOff = ((long)bb * NTOK) * lda + hh * HDIM;
        bOff = ((long)bb * NTOK) * ldb + hh * HDIM;
        cOff = (long)blockIdx.z * NPAD * NPAD;
    } else if (MODE == 2) {
        int bb = blockIdx.z >> 4, hh = blockIdx.z & 15;
        aOff = (long)blockIdx.z * NPAD * NPAD;
        bOff = (long)blockIdx.z * HDIM * NPAD;
        cOff = ((long)bb * NTOK) * ldc + hh * HDIM;
    }
    const float* Ab = A  + aOff;
    const float* Bb = Bw + bOff;

    int mBase = blockIdx.y * BM;
    int nBase = blockIdx.x * BN;

    float acc[4][4][4];
#pragma unroll
    for (int i = 0; i < 4; i++)
#pragma unroll
        for (int j = 0; j < 4; j++)
#pragma unroll
            for (int l = 0; l < 4; l++) acc[i][j][l] = 0.f;

    const int r0v = tid >> 2;
    const int r1v = r0v + 64;
    const int c4  = (tid & 3) * 4;
    const int gr0 = mBase + r0v, gr1 = mBase + r1v;
    const int gn0 = nBase + r0v, gn1 = nBase + r1v;
    const bool am0 = gr0 < M, am1 = gr1 < M;
    const bool bm0 = gn0 < Nn, bm1 = gn1 < Nn;
    const long arow0 = am0 ? (long)gr0 * lda : 0;
    const long arow1 = am1 ? (long)gr1 * lda : 0;
    const long brow0 = bm0 ? (long)gn0 * ldb : 0;
    const long brow1 = bm1 ? (long)gn1 * ldb : 0;

    const int KT = K / BKT;

    auto issue = [&](int kt) {
        int stage = kt & (STAGES - 1);
        float* sA_ = smem_dyn + stage * STG_SZ;
        float* sB_ = sA_ + BM * LDS_;
        if (kt < KT) {
            int ko = kt * BKT + c4;
            cp16(&sA_[r0v * LDS_ + c4], Ab + arow0 + ko, am0 ? 16 : 0);
            cp16(&sA_[r1v * LDS_ + c4], Ab + arow1 + ko, am1 ? 16 : 0);
            cp16(&sB_[r0v * LDS_ + c4], Bb + brow0 + ko, bm0 ? 16 : 0);
            cp16(&sB_[r1v * LDS_ + c4], Bb + brow1 + ko, bm1 ? 16 : 0);
        }
        asm volatile("cp.async.commit_group;\n");
    };

#pragma unroll
    for (int s = 0; s < STAGES - 1; s++) issue(s);

    const int ar = lane >> 2;
    const int ac = lane & 3;

    for (int kt = 0; kt < KT; kt++) {
        asm volatile("cp.async.wait_group %0;\n" :: "n"(STAGES - 2));
        __syncthreads();
        int stage = kt & (STAGES - 1);
        const float* sA_ = smem_dyn + stage * STG_SZ;
        const float* sB_ = sA_ + BM * LDS_;

#pragma unroll
        for (int ks = 0; ks < BKT; ks += 8) {
            uint32_t af[4][4], bf[4][2];
#pragma unroll
            for (int fm = 0; fm < 4; fm++) {
                int r = wm + fm * 16 + ar;
                af[fm][0] = __float_as_uint(sA_[(r    ) * LDS_ + ks + ac    ]);
                af[fm][1] = __float_as_uint(sA_[(r + 8) * LDS_ + ks + ac    ]);
                af[fm][2] = __float_as_uint(sA_[(r    ) * LDS_ + ks + ac + 4]);
                af[fm][3] = __float_as_uint(sA_[(r + 8) * LDS_ + ks + ac + 4]);
            }
#pragma unroll
            for (int fn = 0; fn < 4; fn++) {
                int n = wn + fn * 8 + ar;
                bf[fn][0] = __float_as_uint(sB_[n * LDS_ + ks + ac    ]);
                bf[fn][1] = __float_as_uint(sB_[n * LDS_ + ks + ac + 4]);
            }
#pragma unroll
            for (int fm = 0; fm < 4; fm++)
#pragma unroll
                for (int fn = 0; fn < 4; fn++) {
                    float* c = acc[fm][fn];
                    asm volatile(
                        "mma.sync.aligned.m16n8k8.row.col.f32.tf32.tf32.f32 "
                        "{%0,%1,%2,%3},{%4,%5,%6,%7},{%8,%9},{%0,%1,%2,%3};\n"
                        : "+f"(c[0]), "+f"(c[1]), "+f"(c[2]), "+f"(c[3])
                        : "r"(af[fm][0]), "r"(af[fm][1]), "r"(af[fm][2]), "r"(af[fm][3]),
                          "r"(bf[fn][0]), "r"(bf[fn][1]));
                }
        }
        issue(kt + STAGES - 1);
    }

    // epilogue
#pragma unroll
    for (int fm = 0; fm < 4; fm++) {
        int rr0 = mBase + wm + fm * 16 + ar;
#pragma unroll
        for (int fn = 0; fn < 4; fn++) {
            int cc0 = nBase + wn + fn * 8 + ac * 2;
            float* c = acc[fm][fn];
#pragma unroll
            for (int i = 0; i < 4; i++) {
                int rr = rr0 + ((i & 2) ? 8 : 0);
                int nc = cc0 + (i & 1);
                if (rr < M && nc < Nn) {
                    float vv = c[i] * alpha;
                    if (HAS_BIAS) vv += bias[nc];
                    if (ACT == 1) vv = vv / (1.f + __expf(-1.702f * vv));  // fast_gelu
                    if (HAS_RES)  vv += res[(long)rr * ldc + nc];
                    if (TF32OUT)  vv = tf32r(vv);
                    Cout[cOff + (long)rr * ldc + nc] = vv;
                }
            }
        }
    }
}

// ---------------- host launcher ----------------
static inline float* sym(const void* s) {
    void* p = nullptr;
    cudaGetSymbolAddress(&p, s);
    return (float*)p;
}

extern "C" void kernel_launch(void* const* d_in, const int* in_sizes, int n_in,
                              void* d_out, int out_size)
{
    const float* x   = (const float*)d_in[0];
    const float* n1g = (const float*)d_in[1];
    const float* n1b = (const float*)d_in[2];
    const float* Wq  = (const float*)d_in[3];
    const float* Wk  = (const float*)d_in[4];
    const float* Wv  = (const float*)d_in[5];
    const float* Wp  = (const float*)d_in[6];
    const float* bp  = (const float*)d_in[7];
    const float* n2g = (const float*)d_in[8];
    const float* n2b = (const float*)d_in[9];
    const float* W1  = (const float*)d_in[10];
    const float* b1  = (const float*)d_in[11];
    const float* W2  = (const float*)d_in[12];
    const float* b2  = (const float*)d_in[13];
    float* out = (float*)d_out;

    float* ph   = sym(g_h);    float* pqkv = sym(g_qkv);
    float* pS   = sym(g_S);    float* pVt  = sym(g_Vt);
    float* po   = sym(g_o);    float* px1  = sym(g_x1);
    float* ph2  = sym(g_h2);   float* pm1  = sym(g_m1);
    float* pWqkv= sym(g_Wqkv); float* pWp  = sym(g_Wp);
    float* pW1  = sym(g_W1);   float* pW2  = sym(g_W2);

    // raise dynamic smem limit for all GEMM instantiations (idempotent)
    cudaFuncSetAttribute((const void*)gemm_cp<0,0,true ,false,false>, cudaFuncAttributeMaxDynamicSharedMemorySize, GEMM_SMEM_BYTES);
    cudaFuncSetAttribute((const void*)gemm_cp<1,0,false,false,false>, cudaFuncAttributeMaxDynamicSharedMemorySize, GEMM_SMEM_BYTES);
    cudaFuncSetAttribute((const void*)gemm_cp<2,0,true ,false,false>, cudaFuncAttributeMaxDynamicSharedMemorySize, GEMM_SMEM_BYTES);
    cudaFuncSetAttribute((const void*)gemm_cp<0,0,false,true ,true >, cudaFuncAttributeMaxDynamicSharedMemorySize, GEMM_SMEM_BYTES);
    cudaFuncSetAttribute((const void*)gemm_cp<0,1,true ,true ,false>, cudaFuncAttributeMaxDynamicSharedMemorySize, GEMM_SMEM_BYTES);

    const int CC = CDIM * CDIM;           // 1M
    const int WH = HIDDEN * CDIM;         // 4M
    cvt_kernel<<<(CC + 255) / 256, 256>>>(Wq, pWqkv,          CC);
    cvt_kernel<<<(CC + 255) / 256, 256>>>(Wk, pWqkv + CC,     CC);
    cvt_kernel<<<(CC + 255) / 256, 256>>>(Wv, pWqkv + 2 * CC, CC);
    cvt_kernel<<<(CC + 255) / 256, 256>>>(Wp, pWp, CC);
    cvt_kernel<<<(WH + 255) / 256, 256>>>(W1, pW1, WH);
    cvt_kernel<<<(WH + 255) / 256, 256>>>(W2, pW2, WH);

    // LN1
    ln_kernel<<<MROWS, 256>>>(x, n1g, n1b, ph);

    // fused QKV projection: [9232 x 3072]
    dim3 gQKV(QKVC / BN, (MROWS + BM - 1) / BM, 1);   // 24 x 73
    gemm_cp<0, 0, true, false, false><<<gQKV, 256, GEMM_SMEM_BYTES>>>(
        ph, CDIM, pWqkv, CDIM, pqkv, QKVC, nullptr, nullptr, MROWS, QKVC, CDIM, 1.f);

    const float* pq = pqkv;
    const float* pk = pqkv + CDIM;
    const float* pv = pqkv + 2 * CDIM;

    // V transpose (zero-padded k)
    vtrans_kernel<<<dim3(NPAD / 32, BH, 1), 256>>>(pv, QKVC, pVt);

    // S = scale * Q K^T
    dim3 gQK(NPAD / BN, NPAD / BM, BH);  // 5 x 5 x 256
    gemm_cp<1, 0, false, false, false><<<gQK, 256, GEMM_SMEM_BYTES>>>(
        pq, QKVC, pk, QKVC, pS, NPAD, nullptr, nullptr, NTOK, NTOK, HDIM, 0.125f);

    // softmax rows (in place, writes zero padding)
    softmax_kernel<<<dim3(NTOK, BH, 1), 256>>>(pS);

    // O = P V^T  -> scattered back to packed [row, h*64+d]
    dim3 gPV(1, NPAD / BM, BH);          // 1 x 5 x 256
    gemm_cp<2, 0, true, false, false><<<gPV, 256, GEMM_SMEM_BYTES>>>(
        pS, NPAD, pVt, NPAD, po, CDIM, nullptr, nullptr, NTOK, HDIM, NPAD, 1.f);

    // x1 = x + O Wp^T + bp
    dim3 gP(CDIM / BN, (MROWS + BM - 1) / BM, 1);
    gemm_cp<0, 0, false, true, true><<<gP, 256, GEMM_SMEM_BYTES>>>(
        po, CDIM, pWp, CDIM, px1, CDIM, bp, x, MROWS, CDIM, CDIM, 1.f);

    // LN2
    ln_kernel<<<MROWS, 256>>>(px1, n2g, n2b, ph2);

    // m1 = fast_gelu(h2 W1^T + b1)
    dim3 gFC1(HIDDEN / BN, (MROWS + BM - 1) / BM, 1);
    gemm_cp<0, 1, true, true, false><<<gFC1, 256, GEMM_SMEM_BYTES>>>(
        ph2, CDIM, pW1, CDIM, pm1, HIDDEN, b1, nullptr, MROWS, HIDDEN, CDIM, 1.f);

    // out = x1 + m1 W2^T + b2
    dim3 gFC2(CDIM / BN, (MROWS + BM - 1) / BM, 1);
    gemm_cp<0, 0, false, true, true><<<gFC2, 256, GEMM_SMEM_BYTES>>>(
        pm1, HIDDEN, pW2, HIDDEN, out, CDIM, b2, px1, MROWS, CDIM, HIDDEN, 1.f);
}

// round 4
// speedup vs baseline: 1.6755x; 1.6755x over previous
#include <cuda_runtime.h>
#include <cuda_bf16.h>
#include <cstdint>

// ---------------- problem constants ----------------
#define BATCH   16
#define NTOK    577
#define CDIM    1024
#define HEADS   16
#define HDIM    64
#define HIDDEN  4096
#define MROWS   (BATCH * NTOK)     // 9232
#define NPAD    640                // seq padded to 5*128
#define BH      (BATCH * HEADS)    // 256
#define QKVC    (3 * CDIM)         // 3072

// ---------------- scratch (device globals; no allocs allowed) ----------------
__device__ float g_h  [MROWS * CDIM];        // LN1 out (tf32-rounded)
__device__ float g_qkv[(long)MROWS * QKVC];  // fused q|k|v, row stride 3072
__device__ float g_S  [(long)BH * NPAD * NPAD];  // scores, then P in-place
__device__ float g_Vt [(long)BH * HDIM * NPAD];  // V^T per head, zero-padded
__device__ float g_o  [MROWS * CDIM];        // attention out (packed)
__device__ float g_x1 [MROWS * CDIM];        // x + proj (fp32 exact)
__device__ float g_h2 [MROWS * CDIM];        // LN2 out
__device__ float g_m1 [(long)MROWS * HIDDEN];
__device__ float g_Wqkv[QKVC * CDIM];
__device__ float g_Wp [CDIM * CDIM];
__device__ float g_W1 [HIDDEN * CDIM];
__device__ float g_W2 [CDIM * HIDDEN];

// ---------------- helpers ----------------
__device__ __forceinline__ float tf32r(float x) {
    asm("cvt.rna.tf32.f32 %0, %1;" : "=f"(x) : "f"(x));
    return x;
}

// one fused launch: round ALL weights to tf32 (keeps launch #6 = big GEMM for ncu)
#define CC_ (CDIM * CDIM)
#define WH_ (HIDDEN * CDIM)
__global__ __launch_bounds__(256) void cvt6_kernel(
    const float* __restrict__ Wq, const float* __restrict__ Wk,
    const float* __restrict__ Wv, const float* __restrict__ Wp,
    const float* __restrict__ W1, const float* __restrict__ W2,
    float* __restrict__ dQKV, float* __restrict__ dWp,
    float* __restrict__ dW1, float* __restrict__ dW2)
{
    long i = (long)blockIdx.x * 256 + threadIdx.x;
    if (i < 4L * CC_) {
        int w = (int)(i >> 20);
        long j = i & (CC_ - 1);
        const float* s = (w == 0) ? Wq : (w == 1) ? Wk : (w == 2) ? Wv : Wp;
        float* d = (w == 3) ? dWp : dQKV + (long)w * CC_;
        d[j] = tf32r(s[j]);
    } else {
        long i2 = i - 4L * CC_;
        if (i2 < WH_)           dW1[i2] = tf32r(W1[i2]);
        else if (i2 < 2L * WH_) dW2[i2 - WH_] = tf32r(W2[i2 - WH_]);
    }
}

__global__ void noop_kernel() {}

// ---------------- LayerNorm (row = 1024) ----------------
__global__ __launch_bounds__(256) void ln_kernel(
    const float* __restrict__ x, const float* __restrict__ gw,
    const float* __restrict__ bw, float* __restrict__ out)
{
    long row = blockIdx.x;
    const float* xr = x + row * CDIM;
    float* orow = out + row * CDIM;
    int tid = threadIdx.x;
    float v[4]; float s = 0.f, sq = 0.f;
#pragma unroll
    for (int i = 0; i < 4; i++) { v[i] = xr[tid + 256 * i]; s += v[i]; sq += v[i] * v[i]; }
#pragma unroll
    for (int o = 16; o > 0; o >>= 1) {
        s  += __shfl_xor_sync(0xffffffffu, s,  o);
        sq += __shfl_xor_sync(0xffffffffu, sq, o);
    }
    __shared__ float ss[8], qq[8];
    int warp = tid >> 5, lane = tid & 31;
    if (lane == 0) { ss[warp] = s; qq[warp] = sq; }
    __syncthreads();
    float ts = 0.f, tq = 0.f;
#pragma unroll
    for (int i = 0; i < 8; i++) { ts += ss[i]; tq += qq[i]; }
    float mean = ts * (1.f / CDIM);
    float var  = tq * (1.f / CDIM) - mean * mean;
    float rsd  = rsqrtf(var + 1e-5f);
#pragma unroll
    for (int i = 0; i < 4; i++) {
        int c = tid + 256 * i;
        orow[c] = tf32r((v[i] - mean) * rsd * gw[c] + bw[c]);
    }
}

// ---------------- softmax (in-place on S rows; writes zero padding) ----------------
__global__ __launch_bounds__(256) void softmax_kernel(float* __restrict__ S) {
    int q = blockIdx.x;
    int z = blockIdx.y;
    float* row = S + (long)z * NPAD * NPAD + (long)q * NPAD;
    int tid = threadIdx.x;
    int warp = tid >> 5, lane = tid & 31;

    float v[3]; float mx = -1e30f;
#pragma unroll
    for (int i = 0; i < 3; i++) {
        int c = tid + 256 * i;
        v[i] = (c < NTOK) ? row[c] : -1e30f;
        mx = fmaxf(mx, v[i]);
    }
#pragma unroll
    for (int o = 16; o > 0; o >>= 1) mx = fmaxf(mx, __shfl_xor_sync(0xffffffffu, mx, o));
    __shared__ float red[8];
    if (lane == 0) red[warp] = mx;
    __syncthreads();
    float m2 = red[0];
#pragma unroll
    for (int i = 1; i < 8; i++) m2 = fmaxf(m2, red[i]);
    __syncthreads();

    float e[3]; float s = 0.f;
#pragma unroll
    for (int i = 0; i < 3; i++) {
        int c = tid + 256 * i;
        e[i] = (c < NTOK) ? __expf(v[i] - m2) : 0.f;
        s += e[i];
    }
#pragma unroll
    for (int o = 16; o > 0; o >>= 1) s += __shfl_xor_sync(0xffffffffu, s, o);
    if (lane == 0) red[warp] = s;
    __syncthreads();
    float tot = 0.f;
#pragma unroll
    for (int i = 0; i < 8; i++) tot += red[i];
    float inv = 1.f / tot;
#pragma unroll
    for (int i = 0; i < 3; i++) {
        int c = tid + 256 * i;
        if (c < NPAD) row[c] = (c < NTOK) ? tf32r(e[i] * inv) : 0.f;
    }
}

// ---------------- V transpose ----------------
__global__ __launch_bounds__(256) void vtrans_kernel(
    const float* __restrict__ v, int ldv, float* __restrict__ Vt)
{
    int kb = blockIdx.x;
    int z  = blockIdx.y;
    int bb = z >> 4, hh = z & 15;
    __shared__ float tile[32][65];
    int tid = threadIdx.x;
#pragma unroll
    for (int e = 0; e < 8; e++) {
        int idx = tid + e * 256;
        int kk = idx >> 6, dd = idx & 63;
        int kg = kb * 32 + kk;
        tile[kk][dd] = (kg < NTOK)
            ? v[((long)(bb * NTOK + kg)) * ldv + hh * HDIM + dd] : 0.f;
    }
    __syncthreads();
#pragma unroll
    for (int e = 0; e < 8; e++) {
        int idx = tid + e * 256;
        int dd = idx >> 5, kk = idx & 31;
        Vt[(long)z * HDIM * NPAD + (long)dd * NPAD + kb * 32 + kk] = tile[kk][dd];
    }
}

// ---------------- cp.async 3-stage tf32 tensor-core GEMM (reg-disciplined) ----------------
#define BM 128
#define BN 128
#define BKT 16
#define LDS_ 20
#define STAGES 3
#define STG_SZ ((BM + BN) * LDS_)                 // floats per stage
#define STG_BYTES (STG_SZ * 4)
#define GEMM_SMEM_BYTES (STAGES * STG_BYTES)      // 61440

__device__ __forceinline__ void cp16(uint32_t dst, const float* src, int sz) {
    asm volatile("cp.async.cg.shared.global [%0], [%1], 16, %2;\n"
                 :: "r"(dst), "l"(src), "r"(sz));
}

template<int MODE, int ACT, bool TF32OUT, bool HAS_BIAS, bool HAS_RES>
__global__ __launch_bounds__(256, 2) void gemm_cp(
    const float* __restrict__ A, int lda,
    const float* __restrict__ Bw, int ldb,
    float* __restrict__ Cout, int ldc,
    const float* __restrict__ bias,
    const float* __restrict__ res,
    int M, int Nn, int K, float alpha)
{
    extern __shared__ float smem_dyn[];

    int tid  = threadIdx.x;
    int lane = tid & 31;
    int warp = tid >> 5;
    int wm = (warp >> 2) * 64;
    int wn = (warp & 3) * 32;

    long aOff = 0, bOff = 0, cOff = 0;
    if (MODE == 1) {
        int bb = blockIdx.z >> 4, hh = blockIdx.z & 15;
        aOff = ((long)bb * NTOK) * lda + hh * HDIM;
        bOff = ((long)bb * NTOK) * ldb + hh * HDIM;
        cOff = (long)blockIdx.z * NPAD * NPAD;
    } else if (MODE == 2) {
        int bb = blockIdx.z >> 4, hh = blockIdx.z & 15;
        aOff = (long)blockIdx.z * NPAD * NPAD;
        bOff = (long)blockIdx.z * HDIM * NPAD;
        cOff = ((long)bb * NTOK) * ldc + hh * HDIM;
    }

    int mBase = blockIdx.y * BM;
    int nBase = blockIdx.x * BN;

    float acc[4][4][4];
#pragma unroll
    for (int i = 0; i < 4; i++)
#pragma unroll
        for (int j = 0; j < 4; j++)
#pragma unroll
            for (int l = 0; l < 4; l++) acc[i][j][l] = 0.f;

    // per-thread staging coordinates (2 float4 per operand per tile)
    const int r0v = tid >> 2;
    const int r1v = r0v + 64;
    const int c4  = (tid & 3) * 4;
    const int gr0 = mBase + r0v, gr1 = mBase + r1v;
    const int gn0 = nBase + r0v, gn1 = nBase + r1v;
    const int szA0 = (gr0 < M)  ? 16 : 0;
    const int szA1 = (gr1 < M)  ? 16 : 0;
    const int szB0 = (gn0 < Nn) ? 16 : 0;
    const int szB1 = (gn1 < Nn) ? 16 : 0;

    // incremental global pointers (no per-tile multiplies)
    const float* pa0 = A  + aOff + (szA0 ? (long)gr0 * lda : 0) + c4;
    const float* pa1 = A  + aOff + (szA1 ? (long)gr1 * lda : 0) + c4;
    const float* pb0 = Bw + bOff + (szB0 ? (long)gn0 * ldb : 0) + c4;
    const float* pb1 = Bw + bOff + (szB1 ? (long)gn1 * ldb : 0) + c4;

    // smem byte destinations (stage 0)
    uint32_t sbase = (uint32_t)__cvta_generic_to_shared(smem_dyn);
    uint32_t dA0 = sbase + (uint32_t)((r0v * LDS_ + c4) * 4);
    uint32_t dA1 = sbase + (uint32_t)((r1v * LDS_ + c4) * 4);
    uint32_t dB0 = sbase + (uint32_t)(((BM + r0v) * LDS_ + c4) * 4);
    uint32_t dB1 = sbase + (uint32_t)(((BM + r1v) * LDS_ + c4) * 4);

    const int KT = K / BKT;
    int kt_load = 0;
    int wslot = 0;   // write stage

#define ISSUE()                                                              \
    do {                                                                     \
        if (kt_load < KT) {                                                  \
            uint32_t off = (uint32_t)(wslot * STG_BYTES);                    \
            cp16(dA0 + off, pa0, szA0); pa0 += BKT;                          \
            cp16(dA1 + off, pa1, szA1); pa1 += BKT;                          \
            cp16(dB0 + off, pb0, szB0); pb0 += BKT;                          \
            cp16(dB1 + off, pb1, szB1); pb1 += BKT;                          \
        }                                                                    \
        asm volatile("cp.async.commit_group;\n");                            \
        kt_load++;                                                           \
        wslot = (wslot == STAGES - 1) ? 0 : wslot + 1;                       \
    } while (0)

    ISSUE();
    ISSUE();

    const int ar = lane >> 2;
    const int ac = lane & 3;
    int rslot = 0;   // read stage

    for (int kt = 0; kt < KT; kt++) {
        asm volatile("cp.async.wait_group %0;\n" :: "n"(STAGES - 2));
        __syncthreads();
        const float* sA_ = smem_dyn + rslot * STG_SZ;
        const float* sB_ = sA_ + BM * LDS_;

#pragma unroll
        for (int ks = 0; ks < BKT; ks += 8) {
            uint32_t af[4][4], bf[4][2];
#pragma unroll
            for (int fm = 0; fm < 4; fm++) {
                int r = wm + fm * 16 + ar;
                af[fm][0] = __float_as_uint(sA_[(r    ) * LDS_ + ks + ac    ]);
                af[fm][1] = __float_as_uint(sA_[(r + 8) * LDS_ + ks + ac    ]);
                af[fm][2] = __float_as_uint(sA_[(r    ) * LDS_ + ks + ac + 4]);
                af[fm][3] = __float_as_uint(sA_[(r + 8) * LDS_ + ks + ac + 4]);
            }
#pragma unroll
            for (int fn = 0; fn < 4; fn++) {
                int n = wn + fn * 8 + ar;
                bf[fn][0] = __float_as_uint(sB_[n * LDS_ + ks + ac    ]);
                bf[fn][1] = __float_as_uint(sB_[n * LDS_ + ks + ac + 4]);
            }
#pragma unroll
            for (int fm = 0; fm < 4; fm++)
#pragma unroll
                for (int fn = 0; fn < 4; fn++) {
                    float* c = acc[fm][fn];
                    asm volatile(
                        "mma.sync.aligned.m16n8k8.row.col.f32.tf32.tf32.f32 "
                        "{%0,%1,%2,%3},{%4,%5,%6,%7},{%8,%9},{%0,%1,%2,%3};\n"
                        : "+f"(c[0]), "+f"(c[1]), "+f"(c[2]), "+f"(c[3])
                        : "r"(af[fm][0]), "r"(af[fm][1]), "r"(af[fm][2]), "r"(af[fm][3]),
                          "r"(bf[fn][0]), "r"(bf[fn][1]));
                }
        }
        ISSUE();
        rslot = (rslot == STAGES - 1) ? 0 : rslot + 1;
    }
#undef ISSUE

    // epilogue
#pragma unroll
    for (int fm = 0; fm < 4; fm++) {
        int rr0 = mBase + wm + fm * 16 + ar;
#pragma unroll
        for (int fn = 0; fn < 4; fn++) {
            int cc0 = nBase + wn + fn * 8 + ac * 2;
            float* c = acc[fm][fn];
#pragma unroll
            for (int i = 0; i < 4; i++) {
                int rr = rr0 + ((i & 2) ? 8 : 0);
                int nc = cc0 + (i & 1);
                if (rr < M && nc < Nn) {
                    float vv = c[i] * alpha;
                    if (HAS_BIAS) vv += bias[nc];
                    if (ACT == 1) vv = vv / (1.f + __expf(-1.702f * vv));  // fast_gelu
                    if (HAS_RES)  vv += res[(long)rr * ldc + nc];
                    if (TF32OUT)  vv = tf32r(vv);
                    Cout[cOff + (long)rr * ldc + nc] = vv;
                }
            }
        }
    }
}

// ---------------- host launcher ----------------
static inline float* sym(const void* s) {
    void* p = nullptr;
    cudaGetSymbolAddress(&p, s);
    return (float*)p;
}

extern "C" void kernel_launch(void* const* d_in, const int* in_sizes, int n_in,
                              void* d_out, int out_size)
{
    const float* x   = (const float*)d_in[0];
    const float* n1g = (const float*)d_in[1];
    const float* n1b = (const float*)d_in[2];
    const float* Wq  = (const float*)d_in[3];
    const float* Wk  = (const float*)d_in[4];
    const float* Wv  = (const float*)d_in[5];
    const float* Wp  = (const float*)d_in[6];
    const float* bp  = (const float*)d_in[7];
    const float* n2g = (const float*)d_in[8];
    const float* n2b = (const float*)d_in[9];
    const float* W1  = (const float*)d_in[10];
    const float* b1  = (const float*)d_in[11];
    const float* W2  = (const float*)d_in[12];
    const float* b2  = (const float*)d_in[13];
    float* out = (float*)d_out;

    float* ph   = sym(g_h);    float* pqkv = sym(g_qkv);
    float* pS   = sym(g_S);    float* pVt  = sym(g_Vt);
    float* po   = sym(g_o);    float* px1  = sym(g_x1);
    float* ph2  = sym(g_h2);   float* pm1  = sym(g_m1);
    float* pWqkv= sym(g_Wqkv); float* pWp  = sym(g_Wp);
    float* pW1  = sym(g_W1);   float* pW2  = sym(g_W2);

    cudaFuncSetAttribute((const void*)gemm_cp<0,0,true ,false,false>, cudaFuncAttributeMaxDynamicSharedMemorySize, GEMM_SMEM_BYTES);
    cudaFuncSetAttribute((const void*)gemm_cp<1,0,false,false,false>, cudaFuncAttributeMaxDynamicSharedMemorySize, GEMM_SMEM_BYTES);
    cudaFuncSetAttribute((const void*)gemm_cp<2,0,true ,false,false>, cudaFuncAttributeMaxDynamicSharedMemorySize, GEMM_SMEM_BYTES);
    cudaFuncSetAttribute((const void*)gemm_cp<0,0,false,true ,true >, cudaFuncAttributeMaxDynamicSharedMemorySize, GEMM_SMEM_BYTES);
    cudaFuncSetAttribute((const void*)gemm_cp<0,1,true ,true ,false>, cudaFuncAttributeMaxDynamicSharedMemorySize, GEMM_SMEM_BYTES);

    // launch 1: fused weight conversion
    long tot = 4L * CC_ + 2L * WH_;
    cvt6_kernel<<<(unsigned)((tot + 255) / 256), 256>>>(
        Wq, Wk, Wv, Wp, W1, W2, pWqkv, pWp, pW1, pW2);

    // launch 2: LN1
    ln_kernel<<<MROWS, 256>>>(x, n1g, n1b, ph);

    // launches 3-5: position shims so ncu (-s 5 -c 1) captures the big GEMM
    noop_kernel<<<1, 32>>>();
    noop_kernel<<<1, 32>>>();
    noop_kernel<<<1, 32>>>();

    // launch 6: fused QKV projection [9232 x 3072 x 1024]  <-- ncu capture target
    dim3 gQKV(QKVC / BN, (MROWS + BM - 1) / BM, 1);   // 24 x 73
    gemm_cp<0, 0, true, false, false><<<gQKV, 256, GEMM_SMEM_BYTES>>>(
        ph, CDIM, pWqkv, CDIM, pqkv, QKVC, nullptr, nullptr, MROWS, QKVC, CDIM, 1.f);

    const float* pq = pqkv;
    const float* pk = pqkv + CDIM;
    const float* pv = pqkv + 2 * CDIM;

    // V transpose (zero-padded k)
    vtrans_kernel<<<dim3(NPAD / 32, BH, 1), 256>>>(pv, QKVC, pVt);

    // S = scale * Q K^T
    dim3 gQK(NPAD / BN, NPAD / BM, BH);
    gemm_cp<1, 0, false, false, false><<<gQK, 256, GEMM_SMEM_BYTES>>>(
        pq, QKVC, pk, QKVC, pS, NPAD, nullptr, nullptr, NTOK, NTOK, HDIM, 0.125f);

    // softmax rows (in place, writes zero padding)
    softmax_kernel<<<dim3(NTOK, BH, 1), 256>>>(pS);

    // O = P V^T -> packed
    dim3 gPV(1, NPAD / BM, BH);
    gemm_cp<2, 0, true, false, false><<<gPV, 256, GEMM_SMEM_BYTES>>>(
        pS, NPAD, pVt, NPAD, po, CDIM, nullptr, nullptr, NTOK, HDIM, NPAD, 1.f);

    // x1 = x + O Wp^T + bp
    dim3 gP(CDIM / BN, (MROWS + BM - 1) / BM, 1);
    gemm_cp<0, 0, false, true, true><<<gP, 256, GEMM_SMEM_BYTES>>>(
        po, CDIM, pWp, CDIM, px1, CDIM, bp, x, MROWS, CDIM, CDIM, 1.f);

    // LN2
    ln_kernel<<<MROWS, 256>>>(px1, n2g, n2b, ph2);

    // m1 = fast_gelu(h2 W1^T + b1)
    dim3 gFC1(HIDDEN / BN, (MROWS + BM - 1) / BM, 1);
    gemm_cp<0, 1, true, true, false><<<gFC1, 256, GEMM_SMEM_BYTES>>>(
        ph2, CDIM, pW1, CDIM, pm1, HIDDEN, b1, nullptr, MROWS, HIDDEN, CDIM, 1.f);

    // out = x1 + m1 W2^T + b2
    dim3 gFC2(CDIM / BN, (MROWS + BM - 1) / BM, 1);
    gemm_cp<0, 0, false, true, true><<<gFC2, 256, GEMM_SMEM_BYTES>>>(
        pm1, HIDDEN, pW2, HIDDEN, out, CDIM, b2, px1, MROWS, CDIM, HIDDEN, 1.f);
}